// round 1
// baseline (speedup 1.0000x reference)
#include <cuda_runtime.h>

// Problem constants
static constexpr int B_   = 4;
static constexpr int L_   = 4096;
static constexpr int D_   = 1024;
static constexpr int H_   = 16;
static constexpr int DK_  = 64;
static constexpr int CH_  = 64;            // chunk size
static constexpr int NC_  = L_ / CH_;      // 64 chunks
static constexpr int MR_  = B_ * L_;       // 16384 token rows
static constexpr int NQKV = 3 * D_;        // 3072

// Scratch (device globals: cudaMalloc is forbidden)
__device__ float g_qkv[(size_t)MR_ * NQKV];  // 192 MB: [16384][3072] (q|k|v)
__device__ float g_y  [(size_t)MR_ * D_];    // 64 MB:  [16384][1024]

// ---------------------------------------------------------------------------
// Generic fp32 SGEMM: C[M,N] = A[M,K] @ B[K,N], all row-major.
// 128x128 tile, BK=8, 256 threads, 8x8 microtile. M,N,K multiples of tile dims.
// ---------------------------------------------------------------------------
__global__ __launch_bounds__(256, 2)
void sgemm_nn(const float* __restrict__ A, const float* __restrict__ Bm,
              float* __restrict__ C, int M, int N, int K) {
    __shared__ float As[8][128];   // As[k][m] (transposed A tile)
    __shared__ float Bs[8][128];   // Bs[k][n]

    const int tid  = threadIdx.x;
    const int bm   = blockIdx.y * 128;
    const int bn   = blockIdx.x * 128;
    const int trow = (tid / 16) * 8;
    const int tcol = (tid % 16) * 8;

    // load mapping
    const int arow = tid >> 1;            // 0..127
    const int acol = (tid & 1) * 4;       // 0 or 4
    const int brow = tid >> 5;            // 0..7
    const int bcol = (tid & 31) * 4;      // 0..124

    const float* Aptr = A + (size_t)(bm + arow) * K + acol;
    const float* Bptr = Bm + (size_t)brow * N + bn + bcol;

    float acc[8][8];
#pragma unroll
    for (int i = 0; i < 8; ++i)
#pragma unroll
        for (int j = 0; j < 8; ++j) acc[i][j] = 0.f;

    for (int k0 = 0; k0 < K; k0 += 8) {
        float4 av = *(const float4*)(Aptr + k0);
        float4 bv = *(const float4*)(Bptr + (size_t)k0 * N);
        __syncthreads();
        As[acol + 0][arow] = av.x;
        As[acol + 1][arow] = av.y;
        As[acol + 2][arow] = av.z;
        As[acol + 3][arow] = av.w;
        *(float4*)&Bs[brow][bcol] = bv;
        __syncthreads();
#pragma unroll
        for (int k = 0; k < 8; ++k) {
            float ar[8], br[8];
#pragma unroll
            for (int i = 0; i < 8; ++i) ar[i] = As[k][trow + i];
#pragma unroll
            for (int j = 0; j < 8; ++j) br[j] = Bs[k][tcol + j];
#pragma unroll
            for (int i = 0; i < 8; ++i)
#pragma unroll
                for (int j = 0; j < 8; ++j) acc[i][j] += ar[i] * br[j];
        }
    }

#pragma unroll
    for (int i = 0; i < 8; ++i) {
        float4 v0 = make_float4(acc[i][0], acc[i][1], acc[i][2], acc[i][3]);
        float4 v1 = make_float4(acc[i][4], acc[i][5], acc[i][6], acc[i][7]);
        float* crow = C + (size_t)(bm + trow + i) * N + bn + tcol;
        *(float4*)(crow)     = v0;
        *(float4*)(crow + 4) = v1;
    }
}

// ---------------------------------------------------------------------------
// LayerNorm (no affine) over each head's 64 k-values, in place in g_qkv.
// One warp per (row, head). 8 warps / block.
// ---------------------------------------------------------------------------
__global__ __launch_bounds__(256)
void ln_k_kernel(float* __restrict__ qkv) {
    const int g    = blockIdx.x * 8 + (threadIdx.x >> 5);  // group id
    const int lane = threadIdx.x & 31;
    const int row  = g >> 4;       // /16
    const int h    = g & 15;
    float* p = qkv + (size_t)row * NQKV + D_ + h * DK_;    // k section

    float v0 = p[lane];
    float v1 = p[lane + 32];
    float s = v0 + v1;
#pragma unroll
    for (int o = 16; o > 0; o >>= 1) s += __shfl_xor_sync(0xFFFFFFFFu, s, o);
    const float mu = s * (1.0f / 64.0f);
    const float d0 = v0 - mu, d1 = v1 - mu;
    float ss = d0 * d0 + d1 * d1;
#pragma unroll
    for (int o = 16; o > 0; o >>= 1) ss += __shfl_xor_sync(0xFFFFFFFFu, ss, o);
    const float inv = rsqrtf(ss * (1.0f / 64.0f) + 1e-5f);
    p[lane]      = d0 * inv;
    p[lane + 32] = d1 * inv;
}

// ---------------------------------------------------------------------------
// Chunked linear-attention scan. One CTA per (b,h); sequential over 64 chunks.
// S (64x64) + q/k/v tiles in dynamic smem (padded stride 65). scores aliases Q.
// Each thread: 4x4 microtile of every 64x64 product. 256 threads (16x16).
// ---------------------------------------------------------------------------
static constexpr int PAD_ = 65;
static constexpr int SCAN_SMEM = 4 * 64 * PAD_ * (int)sizeof(float);  // 66560 B

__global__ __launch_bounds__(256, 1)
void scan_kernel(const float* __restrict__ qkv, float* __restrict__ y) {
    extern __shared__ float sm[];
    float* Ssm = sm;                 // state S[d][e]
    float* Qsm = sm + 1 * 64 * PAD_; // q tile, later reused for scores
    float* Ksm = sm + 2 * 64 * PAD_;
    float* Vsm = sm + 3 * 64 * PAD_;

    const int tid = threadIdx.x;
    const int bh  = blockIdx.x;         // 0..63
    const int b   = bh >> 4;
    const int h   = bh & 15;
    const int ty  = tid >> 4;
    const int tx  = tid & 15;
    const int r0  = ty * 4;
    const int c0  = tx * 4;

    // zero S
    for (int i = tid; i < 64 * PAD_; i += 256) Ssm[i] = 0.f;

    const float* qbase = qkv + (size_t)(b * L_) * NQKV + 0 * D_ + h * DK_;
    const float* kbase = qkv + (size_t)(b * L_) * NQKV + 1 * D_ + h * DK_;
    const float* vbase = qkv + (size_t)(b * L_) * NQKV + 2 * D_ + h * DK_;
    float* ybase = y + (size_t)(b * L_) * D_ + h * DK_;

    const int lr = tid >> 2;        // 0..63 (row of tile to load)
    const int lc = (tid & 3) * 16;  // 0,16,32,48

    for (int c = 0; c < NC_; ++c) {
        // ---- load q,k,v tiles (coalesced float4 LDG, scalar STS into padded smem)
        const size_t roff = (size_t)(c * CH_ + lr) * NQKV;
#pragma unroll
        for (int u = 0; u < 4; ++u) {
            const int col = lc + u * 4;
            float4 qv = *(const float4*)(qbase + roff + col);
            float4 kv = *(const float4*)(kbase + roff + col);
            float4 vv = *(const float4*)(vbase + roff + col);
            const int si = lr * PAD_ + col;
            Qsm[si + 0] = qv.x; Qsm[si + 1] = qv.y; Qsm[si + 2] = qv.z; Qsm[si + 3] = qv.w;
            Ksm[si + 0] = kv.x; Ksm[si + 1] = kv.y; Ksm[si + 2] = kv.z; Ksm[si + 3] = kv.w;
            Vsm[si + 0] = vv.x; Vsm[si + 1] = vv.y; Vsm[si + 2] = vv.z; Vsm[si + 3] = vv.w;
        }
        __syncthreads();

        // ---- phase 1: inter[t,d] = sum_e q[t,e]*S[d,e];  scores[t,s] = sum_d q[t,d]*k[s,d]
        float acc1[4][4], acc2[4][4];
#pragma unroll
        for (int i = 0; i < 4; ++i)
#pragma unroll
            for (int j = 0; j < 4; ++j) { acc1[i][j] = 0.f; acc2[i][j] = 0.f; }

#pragma unroll 4
        for (int e = 0; e < 64; ++e) {
            float a[4], bs[4], bk[4];
#pragma unroll
            for (int i = 0; i < 4; ++i) a[i] = Qsm[(r0 + i) * PAD_ + e];
#pragma unroll
            for (int j = 0; j < 4; ++j) bs[j] = Ssm[(c0 + j) * PAD_ + e];
#pragma unroll
            for (int j = 0; j < 4; ++j) bk[j] = Ksm[(c0 + j) * PAD_ + e];
#pragma unroll
            for (int i = 0; i < 4; ++i)
#pragma unroll
                for (int j = 0; j < 4; ++j) {
                    acc1[i][j] += a[i] * bs[j];
                    acc2[i][j] += a[i] * bk[j];
                }
        }
        // causal mask: zero scores where s > t
#pragma unroll
        for (int i = 0; i < 4; ++i)
#pragma unroll
            for (int j = 0; j < 4; ++j)
                if (c0 + j > r0 + i) acc2[i][j] = 0.f;

        __syncthreads();   // everyone done reading Qsm
        // ---- store scores into Qsm (alias)
#pragma unroll
        for (int i = 0; i < 4; ++i)
#pragma unroll
            for (int j = 0; j < 4; ++j)
                Qsm[(r0 + i) * PAD_ + c0 + j] = acc2[i][j];
        __syncthreads();

        // ---- phase 2: intra[t,d] += sum_s sc[t,s]*v[s,d];  dS[d,e] = sum_t v[t,d]*k[t,e]
        float accS[4][4];
#pragma unroll
        for (int i = 0; i < 4; ++i)
#pragma unroll
            for (int j = 0; j < 4; ++j) accS[i][j] = 0.f;

#pragma unroll 4
        for (int t = 0; t < 64; ++t) {
            float sc[4], vB[4], vA[4], kB[4];
#pragma unroll
            for (int i = 0; i < 4; ++i) sc[i] = Qsm[(r0 + i) * PAD_ + t];
#pragma unroll
            for (int j = 0; j < 4; ++j) vB[j] = Vsm[t * PAD_ + c0 + j];
#pragma unroll
            for (int i = 0; i < 4; ++i) vA[i] = Vsm[t * PAD_ + r0 + i];
#pragma unroll
            for (int j = 0; j < 4; ++j) kB[j] = Ksm[t * PAD_ + c0 + j];
#pragma unroll
            for (int i = 0; i < 4; ++i)
#pragma unroll
                for (int j = 0; j < 4; ++j) {
                    acc1[i][j] += sc[i] * vB[j];
                    accS[i][j] += vA[i] * kB[j];
                }
        }

        // ---- write y tile (inter + intra)
#pragma unroll
        for (int i = 0; i < 4; ++i) {
            float4 v = make_float4(acc1[i][0], acc1[i][1], acc1[i][2], acc1[i][3]);
            *(float4*)(ybase + (size_t)(c * CH_ + r0 + i) * D_ + c0) = v;
        }
        // ---- update state S (each element owned by exactly one thread)
#pragma unroll
        for (int i = 0; i < 4; ++i)
#pragma unroll
            for (int j = 0; j < 4; ++j)
                Ssm[(r0 + i) * PAD_ + c0 + j] += accS[i][j];
        __syncthreads();   // protect S writes + V/K reads before next tile load
    }
}

// ---------------------------------------------------------------------------
// kernel_launch: x @ W_qkv -> LN(k) -> chunk scan -> y @ W_o
// ---------------------------------------------------------------------------
extern "C" void kernel_launch(void* const* d_in, const int* in_sizes, int n_in,
                              void* d_out, int out_size) {
    (void)in_sizes; (void)n_in; (void)out_size;
    const float* x    = (const float*)d_in[0];
    const float* Wqkv = (const float*)d_in[1];
    const float* Wo   = (const float*)d_in[2];
    float* out = (float*)d_out;

    float *qkv_p = nullptr, *y_p = nullptr;
    cudaGetSymbolAddress((void**)&qkv_p, g_qkv);
    cudaGetSymbolAddress((void**)&y_p,  g_y);

    // 1) qkv = x @ W_qkv   (16384x1024 @ 1024x3072)
    {
        dim3 grid(NQKV / 128, MR_ / 128);
        sgemm_nn<<<grid, 256>>>(x, Wqkv, qkv_p, MR_, NQKV, D_);
    }
    // 2) layernorm k in place
    {
        const int groups = MR_ * H_;             // 262144
        ln_k_kernel<<<groups / 8, 256>>>(qkv_p);
    }
    // 3) chunked linear attention scan
    {
        cudaFuncSetAttribute(scan_kernel,
                             cudaFuncAttributeMaxDynamicSharedMemorySize, SCAN_SMEM);
        scan_kernel<<<B_ * H_, 256, SCAN_SMEM>>>(qkv_p, y_p);
    }
    // 4) out = y @ W_o     (16384x1024 @ 1024x1024)
    {
        dim3 grid(D_ / 128, MR_ / 128);
        sgemm_nn<<<grid, 256>>>(y_p, Wo, out, MR_, D_, D_);
    }
}

// round 6
// speedup vs baseline: 2.3260x; 2.3260x over previous
#include <cuda_runtime.h>

// Problem constants
static constexpr int B_   = 4;
static constexpr int L_   = 4096;
static constexpr int D_   = 1024;
static constexpr int H_   = 16;
static constexpr int DK_  = 64;
static constexpr int CH_  = 64;
static constexpr int NC_  = L_ / CH_;      // 64
static constexpr int MR_  = B_ * L_;       // 16384
static constexpr int NQKV = 3 * D_;        // 3072
static constexpr int BH_  = B_ * H_;       // 64

// Scratch (device globals: cudaMalloc is forbidden)
__device__ float g_qkv[(size_t)MR_ * NQKV];          // 192 MB
__device__ float g_y  [(size_t)MR_ * D_];            // 64 MB
__device__ float g_G  [(size_t)BH_ * NC_ * 64 * 64]; // 67 MB: [bh][c][d][e]

__device__ __forceinline__ unsigned f2tf(float x) {
    unsigned u;
    asm("cvt.rna.tf32.f32 %0, %1;" : "=r"(u) : "f"(x));
    return u;
}

// ---------------------------------------------------------------------------
// tf32 tensor-core GEMM: C[M,N] = A[M,K] @ B[K,N], row-major.
// 128x128 CTA tile, BK=32, 8 warps (warp tile 64x32), mma.m16n8k8.
// SMEM double-buffered, padded stride 136. M,N mult of 128; K mult of 32.
// ---------------------------------------------------------------------------
static constexpr int GP = 136;                                  // padded row (u32 units)
static constexpr int GEMM_SMEM = 2 * 2 * 32 * GP * (int)sizeof(unsigned); // 69632 B

__global__ __launch_bounds__(256)
void gemm_tf32(const float* __restrict__ A, const float* __restrict__ B,
               float* __restrict__ C, int M, int N, int K) {
    extern __shared__ unsigned sm_u[];
    unsigned* As = sm_u;               // [2][32][GP]  (k-major rows, m across)
    unsigned* Bs = sm_u + 2 * 32 * GP; // [2][32][GP]  (k-major rows, n across)

    const int tid  = threadIdx.x;
    const int bm   = blockIdx.y * 128;
    const int bn   = blockIdx.x * 128;
    const int wid  = tid >> 5;
    const int lane = tid & 31;
    const int wm   = (wid >> 2) * 64;  // 2 warp-rows
    const int wn   = (wid & 3) * 32;   // 4 warp-cols
    const int qr   = lane >> 2;        // 0..7
    const int qc   = lane & 3;         // 0..3

    // A load mapping: thread -> row m=tid>>1, k-quarter (tid&1)*16, 4x float4
    const int am  = tid >> 1;
    const int akq = (tid & 1) * 16;
    const float* Ap = A + (size_t)(bm + am) * K + akq;
    // B load mapping: row r=tid>>3 (k), cols (tid&7)*4 + 32*i
    const int br = tid >> 3;
    const int bc = (tid & 7) * 4;
    const float* Bp = B + (size_t)br * N + bn + bc;

    float4 ra[4], rb[4];

    auto LOADG = [&](int kt) {
        const int k0 = kt * 32;
#pragma unroll
        for (int i = 0; i < 4; ++i) ra[i] = *(const float4*)(Ap + k0 + 4 * i);
#pragma unroll
        for (int i = 0; i < 4; ++i) rb[i] = *(const float4*)(Bp + (size_t)k0 * N + 32 * i);
    };
    auto STORES = [&](int buf) {
        unsigned* Ab = As + buf * 32 * GP;
        unsigned* Bb = Bs + buf * 32 * GP;
#pragma unroll
        for (int i = 0; i < 4; ++i) {
            const float* f = (const float*)&ra[i];
#pragma unroll
            for (int j = 0; j < 4; ++j) Ab[(akq + 4 * i + j) * GP + am] = f2tf(f[j]);
        }
#pragma unroll
        for (int i = 0; i < 4; ++i) {
            uint4 p;
            p.x = f2tf(rb[i].x); p.y = f2tf(rb[i].y);
            p.z = f2tf(rb[i].z); p.w = f2tf(rb[i].w);
            *(uint4*)&Bb[br * GP + bc + 32 * i] = p;
        }
    };

    float c_[4][4][4];
#pragma unroll
    for (int mm = 0; mm < 4; ++mm)
#pragma unroll
        for (int nn = 0; nn < 4; ++nn)
#pragma unroll
            for (int r = 0; r < 4; ++r) c_[mm][nn][r] = 0.f;

    const int NT = K / 32;
    LOADG(0);
    STORES(0);
    __syncthreads();

    for (int kt = 0; kt < NT; ++kt) {
        if (kt + 1 < NT) LOADG(kt + 1);
        const unsigned* Ab = As + (kt & 1) * 32 * GP;
        const unsigned* Bb = Bs + (kt & 1) * 32 * GP;
#pragma unroll
        for (int kk = 0; kk < 4; ++kk) {
            const int k8 = kk * 8;
            unsigned af[4][4], bf[4][2];
#pragma unroll
            for (int mm = 0; mm < 4; ++mm) {
                const int m0 = wm + mm * 16;
                af[mm][0] = Ab[(k8 + qc) * GP + m0 + qr];
                af[mm][1] = Ab[(k8 + qc) * GP + m0 + qr + 8];
                af[mm][2] = Ab[(k8 + qc + 4) * GP + m0 + qr];
                af[mm][3] = Ab[(k8 + qc + 4) * GP + m0 + qr + 8];
            }
#pragma unroll
            for (int nn = 0; nn < 4; ++nn) {
                const int n0 = wn + nn * 8;
                bf[nn][0] = Bb[(k8 + qc) * GP + n0 + qr];
                bf[nn][1] = Bb[(k8 + qc + 4) * GP + n0 + qr];
            }
#pragma unroll
            for (int mm = 0; mm < 4; ++mm)
#pragma unroll
                for (int nn = 0; nn < 4; ++nn) {
                    asm volatile(
                        "mma.sync.aligned.m16n8k8.row.col.f32.tf32.tf32.f32 "
                        "{%0,%1,%2,%3}, {%4,%5,%6,%7}, {%8,%9}, {%0,%1,%2,%3};"
                        : "+f"(c_[mm][nn][0]), "+f"(c_[mm][nn][1]),
                          "+f"(c_[mm][nn][2]), "+f"(c_[mm][nn][3])
                        : "r"(af[mm][0]), "r"(af[mm][1]), "r"(af[mm][2]), "r"(af[mm][3]),
                          "r"(bf[nn][0]), "r"(bf[nn][1]));
                }
        }
        if (kt + 1 < NT) {
            STORES((kt + 1) & 1);
            __syncthreads();
        }
    }

    // epilogue
#pragma unroll
    for (int mm = 0; mm < 4; ++mm)
#pragma unroll
        for (int nn = 0; nn < 4; ++nn) {
            const int row = bm + wm + mm * 16 + qr;
            const int col = bn + wn + nn * 8 + qc * 2;
            *(float2*)&C[(size_t)row * N + col] =
                make_float2(c_[mm][nn][0], c_[mm][nn][1]);
            *(float2*)&C[(size_t)(row + 8) * N + col] =
                make_float2(c_[mm][nn][2], c_[mm][nn][3]);
        }
}

// ---------------------------------------------------------------------------
// LayerNorm (no affine) over each head's 64 k-values, in place.
// ---------------------------------------------------------------------------
__global__ __launch_bounds__(256)
void ln_k_kernel(float* __restrict__ qkv) {
    const int g    = blockIdx.x * 8 + (threadIdx.x >> 5);
    const int lane = threadIdx.x & 31;
    const int row  = g >> 4;
    const int h    = g & 15;
    float* p = qkv + (size_t)row * NQKV + D_ + h * DK_;

    float v0 = p[lane];
    float v1 = p[lane + 32];
    float s = v0 + v1;
#pragma unroll
    for (int o = 16; o > 0; o >>= 1) s += __shfl_xor_sync(0xFFFFFFFFu, s, o);
    const float mu = s * (1.0f / 64.0f);
    const float d0 = v0 - mu, d1 = v1 - mu;
    float ss = d0 * d0 + d1 * d1;
#pragma unroll
    for (int o = 16; o > 0; o >>= 1) ss += __shfl_xor_sync(0xFFFFFFFFu, ss, o);
    const float inv = rsqrtf(ss * (1.0f / 64.0f) + 1e-5f);
    p[lane]      = d0 * inv;
    p[lane + 32] = d1 * inv;
}

// ---------------------------------------------------------------------------
// Per-chunk Gram: G[bh][c][d][e] = sum_t v[t,d] * k[t,e].  4096 CTAs.
// ---------------------------------------------------------------------------
__global__ __launch_bounds__(256)
void chunk_state(const float* __restrict__ qkv, float* __restrict__ G) {
    __shared__ float Ks[64][65], Vs[64][65];
    const int bid = blockIdx.x;          // bh*64 + c
    const int c   = bid & 63;
    const int bh  = bid >> 6;
    const int b   = bh >> 4;
    const int h   = bh & 15;
    const int tid = threadIdx.x;

    const float* kb = qkv + (size_t)(b * L_ + c * CH_) * NQKV + D_ + h * DK_;
    const float* vb = kb + D_;

    const int lr = tid >> 2;
    const int lc = (tid & 3) * 16;
#pragma unroll
    for (int u = 0; u < 4; ++u) {
        const int col = lc + u * 4;
        float4 kv = *(const float4*)(kb + (size_t)lr * NQKV + col);
        float4 vv = *(const float4*)(vb + (size_t)lr * NQKV + col);
        Ks[lr][col + 0] = kv.x; Ks[lr][col + 1] = kv.y;
        Ks[lr][col + 2] = kv.z; Ks[lr][col + 3] = kv.w;
        Vs[lr][col + 0] = vv.x; Vs[lr][col + 1] = vv.y;
        Vs[lr][col + 2] = vv.z; Vs[lr][col + 3] = vv.w;
    }
    __syncthreads();

    const int r0 = (tid >> 4) * 4;
    const int c0 = (tid & 15) * 4;
    float acc[4][4];
#pragma unroll
    for (int i = 0; i < 4; ++i)
#pragma unroll
        for (int j = 0; j < 4; ++j) acc[i][j] = 0.f;

#pragma unroll 4
    for (int t = 0; t < 64; ++t) {
        float va[4], kv[4];
#pragma unroll
        for (int i = 0; i < 4; ++i) va[i] = Vs[t][r0 + i];
#pragma unroll
        for (int j = 0; j < 4; ++j) kv[j] = Ks[t][c0 + j];
#pragma unroll
        for (int i = 0; i < 4; ++i)
#pragma unroll
            for (int j = 0; j < 4; ++j) acc[i][j] += va[i] * kv[j];
    }

    float* Gp = G + (size_t)bid * 4096;
#pragma unroll
    for (int i = 0; i < 4; ++i)
        *(float4*)&Gp[(r0 + i) * 64 + c0] =
            make_float4(acc[i][0], acc[i][1], acc[i][2], acc[i][3]);
}

// ---------------------------------------------------------------------------
// Exclusive prefix over chunks, in place. One thread per (bh, d, e) element.
// ---------------------------------------------------------------------------
__global__ __launch_bounds__(256)
void prefix_state(float* __restrict__ G) {
    const int gid = blockIdx.x * 256 + threadIdx.x;   // 262144 total
    const int bh  = gid >> 12;
    const int e   = gid & 4095;
    float* p = G + (size_t)bh * NC_ * 4096 + e;
    float acc = 0.f;
#pragma unroll 4
    for (int c = 0; c < NC_; ++c) {
        float t = p[(size_t)c * 4096];
        p[(size_t)c * 4096] = acc;
        acc += t;
    }
}

// ---------------------------------------------------------------------------
// Per-chunk output: y = Q "@" S^T + tril(Q K^T) V.  4096 CTAs, fully parallel.
// ---------------------------------------------------------------------------
static constexpr int PAD_ = 65;
static constexpr int OUT_SMEM = 4 * 64 * PAD_ * (int)sizeof(float);  // 66560 B

__global__ __launch_bounds__(256)
void chunk_out(const float* __restrict__ qkv, const float* __restrict__ G,
               float* __restrict__ y) {
    extern __shared__ float sm[];
    float* Ssm = sm;
    float* Qsm = sm + 1 * 64 * PAD_;   // later aliased by scores
    float* Ksm = sm + 2 * 64 * PAD_;
    float* Vsm = sm + 3 * 64 * PAD_;

    const int bid = blockIdx.x;        // bh*64 + c
    const int c   = bid & 63;
    const int bh  = bid >> 6;
    const int b   = bh >> 4;
    const int h   = bh & 15;
    const int tid = threadIdx.x;
    const int r0  = (tid >> 4) * 4;
    const int c0  = (tid & 15) * 4;

    const float* qb = qkv + (size_t)(b * L_ + c * CH_) * NQKV + h * DK_;
    const float* kb = qb + D_;
    const float* vb = qb + 2 * D_;
    const float* Gp = G + (size_t)bid * 4096;
    float* yb = y + (size_t)(b * L_ + c * CH_) * D_ + h * DK_;

    const int lr = tid >> 2;
    const int lc = (tid & 3) * 16;
#pragma unroll
    for (int u = 0; u < 4; ++u) {
        const int col = lc + u * 4;
        float4 sv = *(const float4*)(Gp + lr * 64 + col);
        float4 qv = *(const float4*)(qb + (size_t)lr * NQKV + col);
        float4 kv = *(const float4*)(kb + (size_t)lr * NQKV + col);
        float4 vv = *(const float4*)(vb + (size_t)lr * NQKV + col);
        const int si = lr * PAD_ + col;
        Ssm[si + 0] = sv.x; Ssm[si + 1] = sv.y; Ssm[si + 2] = sv.z; Ssm[si + 3] = sv.w;
        Qsm[si + 0] = qv.x; Qsm[si + 1] = qv.y; Qsm[si + 2] = qv.z; Qsm[si + 3] = qv.w;
        Ksm[si + 0] = kv.x; Ksm[si + 1] = kv.y; Ksm[si + 2] = kv.z; Ksm[si + 3] = kv.w;
        Vsm[si + 0] = vv.x; Vsm[si + 1] = vv.y; Vsm[si + 2] = vv.z; Vsm[si + 3] = vv.w;
    }
    __syncthreads();

    // phase 1: inter[t,d] = sum_e q[t,e] S[d,e];  scores[t,s] = sum_d q[t,d] k[s,d]
    float acc1[4][4], acc2[4][4];
#pragma unroll
    for (int i = 0; i < 4; ++i)
#pragma unroll
        for (int j = 0; j < 4; ++j) { acc1[i][j] = 0.f; acc2[i][j] = 0.f; }

#pragma unroll 4
    for (int e = 0; e < 64; ++e) {
        float a[4], bs[4], bk[4];
#pragma unroll
        for (int i = 0; i < 4; ++i) a[i] = Qsm[(r0 + i) * PAD_ + e];
#pragma unroll
        for (int j = 0; j < 4; ++j) bs[j] = Ssm[(c0 + j) * PAD_ + e];
#pragma unroll
        for (int j = 0; j < 4; ++j) bk[j] = Ksm[(c0 + j) * PAD_ + e];
#pragma unroll
        for (int i = 0; i < 4; ++i)
#pragma unroll
            for (int j = 0; j < 4; ++j) {
                acc1[i][j] += a[i] * bs[j];
                acc2[i][j] += a[i] * bk[j];
            }
    }
    // causal mask
#pragma unroll
    for (int i = 0; i < 4; ++i)
#pragma unroll
        for (int j = 0; j < 4; ++j)
            if (c0 + j > r0 + i) acc2[i][j] = 0.f;

    __syncthreads();
#pragma unroll
    for (int i = 0; i < 4; ++i)
#pragma unroll
        for (int j = 0; j < 4; ++j)
            Qsm[(r0 + i) * PAD_ + c0 + j] = acc2[i][j];
    __syncthreads();

    // phase 2: intra[t,d] += sum_s sc[t,s] v[s,d]
#pragma unroll 4
    for (int t = 0; t < 64; ++t) {
        float sc[4], vB[4];
#pragma unroll
        for (int i = 0; i < 4; ++i) sc[i] = Qsm[(r0 + i) * PAD_ + t];
#pragma unroll
        for (int j = 0; j < 4; ++j) vB[j] = Vsm[t * PAD_ + c0 + j];
#pragma unroll
        for (int i = 0; i < 4; ++i)
#pragma unroll
            for (int j = 0; j < 4; ++j) acc1[i][j] += sc[i] * vB[j];
    }

#pragma unroll
    for (int i = 0; i < 4; ++i)
        *(float4*)(yb + (size_t)(r0 + i) * D_ + c0) =
            make_float4(acc1[i][0], acc1[i][1], acc1[i][2], acc1[i][3]);
}

// ---------------------------------------------------------------------------
extern "C" void kernel_launch(void* const* d_in, const int* in_sizes, int n_in,
                              void* d_out, int out_size) {
    (void)in_sizes; (void)n_in; (void)out_size;
    const float* x    = (const float*)d_in[0];
    const float* Wqkv = (const float*)d_in[1];
    const float* Wo   = (const float*)d_in[2];
    float* out = (float*)d_out;

    float *qkv_p = nullptr, *y_p = nullptr, *G_p = nullptr;
    cudaGetSymbolAddress((void**)&qkv_p, g_qkv);
    cudaGetSymbolAddress((void**)&y_p,  g_y);
    cudaGetSymbolAddress((void**)&G_p,  g_G);

    cudaFuncSetAttribute(gemm_tf32,
                         cudaFuncAttributeMaxDynamicSharedMemorySize, GEMM_SMEM);
    cudaFuncSetAttribute(chunk_out,
                         cudaFuncAttributeMaxDynamicSharedMemorySize, OUT_SMEM);

    // 1) qkv = x @ W_qkv
    gemm_tf32<<<dim3(NQKV / 128, MR_ / 128), 256, GEMM_SMEM>>>(
        x, Wqkv, qkv_p, MR_, NQKV, D_);
    // 2) layernorm(k) in place
    ln_k_kernel<<<(MR_ * H_) / 8, 256>>>(qkv_p);
    // 3) per-chunk Gram matrices
    chunk_state<<<BH_ * NC_, 256>>>(qkv_p, G_p);
    // 4) exclusive prefix over chunks -> running states
    prefix_state<<<(BH_ * 4096) / 256, 256>>>(G_p);
    // 5) per-chunk outputs (fully parallel)
    chunk_out<<<BH_ * NC_, 256, OUT_SMEM>>>(qkv_p, G_p, y_p);
    // 6) out = y @ W_o
    gemm_tf32<<<dim3(D_ / 128, MR_ / 128), 256, GEMM_SMEM>>>(
        y_p, Wo, out, MR_, D_, D_);
}